// round 17
// baseline (speedup 1.0000x reference)
#include <cuda_runtime.h>
#include <cuda_fp16.h>
#include <math.h>
#include <cstdint>

#define BATCH 2
#define NH    8
#define SEQ   4096
#define HD    64
#define WRD   512
#define MTOT  (BATCH*SEQ)     // 8192
#define NQKV  640             // 64 (K) + 64 (V) + 8*64 (Q)
#define NKT2  (SEQ/128)       // 32 key tiles of 128

// Q pre-scale: (1/sqrt(64)) * log2(e)  -> scores in log2 domain, exp2 for softmax
#define QSCALE 0.18033688011112042f

// ---------------- scratch (device globals; no allocation allowed) ----------------
__device__ __half g_xh[MTOT*WRD];            // x fp16 [8192,512]
__device__ __half g_WhT[NQKV*WRD];           // packed QKV weight, transposed [n][k] fp16
__device__ __half g_WpT[HD*WRD];             // Wp transposed [n][k] fp16
__device__ float  g_ball[NQKV];              // packed QKV bias fp32
__device__ __half g_Kh[BATCH*SEQ*HD];        // K  [b,t,d] fp16
__device__ __half g_Vth[BATCH*HD*SEQ];       // V^T [b,d,t] fp16
__device__ __half g_Qh[BATCH*NH*SEQ*HD];     // Q  [b,h,s,d] fp16 (pre-scaled)

#define SW128(off) ((off) ^ (((off) >> 3) & 0x70))

__device__ __forceinline__ uint32_t smem_u32(const void* p) {
    uint32_t a;
    asm("{ .reg .u64 t; cvta.to.shared.u64 t, %1; cvt.u32.u64 %0, t; }" : "=r"(a) : "l"(p));
    return a;
}
__device__ __forceinline__ void mma16816(float c[4], const uint32_t a[4], const uint32_t b[2]) {
    asm volatile("mma.sync.aligned.m16n8k16.row.col.f32.f16.f16.f32 "
        "{%0,%1,%2,%3}, {%4,%5,%6,%7}, {%8,%9}, {%0,%1,%2,%3};"
        : "+f"(c[0]), "+f"(c[1]), "+f"(c[2]), "+f"(c[3])
        : "r"(a[0]), "r"(a[1]), "r"(a[2]), "r"(a[3]), "r"(b[0]), "r"(b[1]));
}
// fp16-accumulated MMA: c-frag (2 regs) doubles as the P a-frag after in-place exp
__device__ __forceinline__ void mma16816_f16(uint32_t c[2], const uint32_t a[4], const uint32_t b[2]) {
    asm volatile("mma.sync.aligned.m16n8k16.row.col.f16.f16.f16.f16 "
        "{%0,%1}, {%2,%3,%4,%5}, {%6,%7}, {%0,%1};"
        : "+r"(c[0]), "+r"(c[1])
        : "r"(a[0]), "r"(a[1]), "r"(a[2]), "r"(a[3]), "r"(b[0]), "r"(b[1]));
}
__device__ __forceinline__ void ldsm_x4(uint32_t d[4], uint32_t addr) {
    asm volatile("ldmatrix.sync.aligned.m8n8.x4.shared.b16 {%0,%1,%2,%3}, [%4];"
        : "=r"(d[0]), "=r"(d[1]), "=r"(d[2]), "=r"(d[3]) : "r"(addr));
}
__device__ __forceinline__ void cp16(uint32_t sdst, const void* gsrc) {
    asm volatile("cp.async.cg.shared.global [%0], [%1], 16;" :: "r"(sdst), "l"(gsrc));
}
#define CP_COMMIT() asm volatile("cp.async.commit_group;" ::: "memory")
#define CP_WAIT(n)  asm volatile("cp.async.wait_group %0;" :: "n"(n) : "memory")

// ---------------- kernel 1: merged prep (x-convert + transposes + bias + out-init) ----------------
// grid = 1024 (x, 16 elems/thread) + 352 (transpose) + 1 (bias) + 512 (out init) = 1889 blocks.
__global__ __launch_bounds__(256) void prep2_kernel(
    const float* __restrict__ x,
    const float* __restrict__ Wk, const float* __restrict__ bk,
    const float* __restrict__ Wv, const float* __restrict__ bv,
    const float* __restrict__ Wq, const float* __restrict__ bq,
    const float* __restrict__ Wp, const float* __restrict__ bp,
    float* __restrict__ out)
{
    const int bid = blockIdx.x;
    const int tid = threadIdx.x;

    if (bid < 1024) {
        size_t idx = ((size_t)bid * 256 + tid) * 16;
        float4 a0 = *(const float4*)(x + idx);
        float4 a1 = *(const float4*)(x + idx + 4);
        float4 a2 = *(const float4*)(x + idx + 8);
        float4 a3 = *(const float4*)(x + idx + 12);
        __half2 h0[4] = { __floats2half2_rn(a0.x, a0.y), __floats2half2_rn(a0.z, a0.w),
                          __floats2half2_rn(a1.x, a1.y), __floats2half2_rn(a1.z, a1.w) };
        __half2 h1[4] = { __floats2half2_rn(a2.x, a2.y), __floats2half2_rn(a2.z, a2.w),
                          __floats2half2_rn(a3.x, a3.y), __floats2half2_rn(a3.z, a3.w) };
        *(uint4*)(g_xh + idx)     = *(uint4*)&h0[0];
        *(uint4*)(g_xh + idx + 8) = *(uint4*)&h1[0];
        return;
    }
    if (bid < 1024 + 352) {
        __shared__ float t[32][33];
        int bid2 = bid - 1024;
        int slab = bid2 >> 5, tt = bid2 & 31;
        int k0 = (tt & 15) * 32, n0 = (tt >> 4) * 32;
        const float* src;
        __half* dst;
        if (slab == 0)      src = Wk;
        else if (slab == 1) src = Wv;
        else if (slab < 10) src = Wq + (size_t)(slab-2)*WRD*HD;
        else                src = Wp;
        dst = (slab < 10) ? (g_WhT + (size_t)slab*64*WRD) : g_WpT;

        int tx = tid & 31, ty = tid >> 5;   // 32 x 8
        #pragma unroll
        for (int r = 0; r < 4; r++)
            t[ty + r*8][tx] = src[(size_t)(k0 + ty + r*8)*HD + n0 + tx];
        __syncthreads();
        #pragma unroll
        for (int r = 0; r < 4; r++) {
            int n = ty + r*8;
            dst[(size_t)(n0 + n)*WRD + k0 + tx] = __float2half_rn(t[tx][n]);
        }
        return;
    }
    if (bid == 1024 + 352) {
        for (int i = tid; i < NQKV; i += 256) {
            float v;
            if (i < 64)       v = bk[i];
            else if (i < 128) v = bv[i-64];
            else              v = bq[i-128];
            g_ball[i] = v;
        }
        return;
    }
    {
        int idx = (bid - 1025 - 352) * 256 + tid;    // float4 index, 131072 total
        int col = (idx & 15) * 4;
        float4 bv4 = *(const float4*)(bp + col);
        *(float4*)(out + (size_t)idx*4) = bv4;
    }
}

// ---------------- kernel 2: QKV projection, m32 warp tiles, cp.async double-buffered ----------------
// grid (64, 10), 128 thr (4 warps x 32 m-rows). Tile 128m x 64n, K-step 64. 48KB static smem.
__global__ __launch_bounds__(128) void qkv_mma_kernel()
{
    __shared__ __align__(128) char sA[2][128*128];   // 2 x 16KB
    __shared__ __align__(128) char sB[2][64*128];    // 2 x  8KB

    const int tid = threadIdx.x;
    const int wid = tid >> 5, lane = tid & 31;
    const int m0 = blockIdx.x * 128, n0 = blockIdx.y * 64;

    auto load_tiles = [&](int buf, int k0) {
        #pragma unroll
        for (int r = 0; r < 8; r++) {
            int i = tid + r*128;
            int row = i >> 3, c8 = (i & 7) * 8;
            cp16(smem_u32(sA[buf]) + SW128((uint32_t)(row*128 + c8*2)),
                 g_xh + (size_t)(m0 + row)*WRD + k0 + c8);
        }
        #pragma unroll
        for (int r = 0; r < 4; r++) {
            int i = tid + r*128;
            int row = i >> 3, c8 = (i & 7) * 8;
            cp16(smem_u32(sB[buf]) + SW128((uint32_t)(row*128 + c8*2)),
                 g_WhT + (size_t)(n0 + row)*WRD + k0 + c8);
        }
    };

    float acc[2][8][4] = {};
    const uint32_t colb = (uint32_t)((lane & 8) ? 16 : 0);
    const uint32_t rwb  = (uint32_t)(((lane & 16) ? 8 : 0) + (lane & 7));

    load_tiles(0, 0); CP_COMMIT();

    for (int ki = 0; ki < 8; ki++) {
        if (ki < 7) { load_tiles((ki+1)&1, (ki+1)*64); CP_COMMIT(); CP_WAIT(1); }
        else CP_WAIT(0);
        __syncthreads();

        const uint32_t ab = smem_u32(sA[ki&1]), bb = smem_u32(sB[ki&1]);
        #pragma unroll
        for (int kk = 0; kk < 4; kk++) {
            uint32_t afr[2][4];
            #pragma unroll
            for (int a = 0; a < 2; a++) {
                int row = wid*32 + a*16 + (lane & 7) + ((lane >> 3) & 1) * 8;
                uint32_t col = (uint32_t)(kk*32 + ((lane >> 4) ? 16 : 0));
                ldsm_x4(afr[a], ab + SW128((uint32_t)row*128 + col));
            }
            uint32_t cc = (uint32_t)(kk*32) + colb;
            #pragma unroll
            for (int j2 = 0; j2 < 4; j2++) {
                uint32_t bfr[4];
                ldsm_x4(bfr, bb + SW128((j2*16 + rwb)*128 + cc));
                #pragma unroll
                for (int a = 0; a < 2; a++) {
                    mma16816(acc[a][2*j2],   afr[a], bfr);
                    mma16816(acc[a][2*j2+1], afr[a], bfr + 2);
                }
            }
        }
        __syncthreads();
    }

    // ---- epilogue: bias + scatter to K / V^T / Q ----
    #pragma unroll
    for (int a = 0; a < 2; a++) {
        int r = wid*32 + a*16 + (lane >> 2);
        #pragma unroll
        for (int j = 0; j < 8; j++) {
            #pragma unroll
            for (int e = 0; e < 2; e++) {
                int n = n0 + j*8 + (lane & 3)*2 + e;
                float bias = g_ball[n];
                #pragma unroll
                for (int rr = 0; rr < 2; rr++) {
                    int m = m0 + r + rr*8;
                    float v = acc[a][j][rr*2 + e] + bias;
                    int b = m >> 12, s = m & 4095;
                    if (n < 64) {
                        g_Kh[((size_t)b*SEQ + s)*HD + n] = __float2half_rn(v);
                    } else if (n < 128) {
                        g_Vth[((size_t)b*HD + (n-64))*SEQ + s] = __float2half_rn(v);
                    } else {
                        int nn = n - 128; int h = nn >> 6, d = nn & 63;
                        g_Qh[(((size_t)b*NH + h)*SEQ + s)*HD + d] = __float2half_rn(v * QSCALE);
                    }
                }
            }
        }
    }
}

// ---------------- kernel 3: flash attention + fused output projection ----------------
// grid (SEQ/256, NH, BATCH) = 256 CTAs, 256 threads = 8 warps x 32 q-rows, 1 CTA/SM.
// 8 warps share each 32KB K/V tile -> smem crossbar traffic per MAC halves vs 128q tiles;
// tensor becomes the sole binder. Mainloop structure otherwise frozen (round-16 config).
__global__ __launch_bounds__(256, 1) void attn_mma_kernel(float* __restrict__ out)
{
    extern __shared__ __align__(128) char smemAll[];   // 3 x 32768; slot2 doubles as Q staging (32KB)

    const int tid  = threadIdx.x;
    const int wid  = tid >> 5, lane = tid & 31;
    const int b = blockIdx.z, hh = blockIdx.y, q0 = blockIdx.x * 256;

    const __half* Qp = g_Qh + ((size_t)(b*NH + hh)*SEQ + q0) * HD;
    const __half* Kp = g_Kh  + (size_t)b*SEQ*HD;
    const __half* Vp = g_Vth + (size_t)b*HD*SEQ;

    auto kbuf = [&](int r) -> char* { return smemAll + r*32768; };
    auto vbuf = [&](int r) -> char* { return smemAll + r*32768 + 16384; };
    char* sQ = smemAll + 2*32768;

    auto load_kv = [&](int slot, int kt) {
        char* kb = kbuf(slot); char* vb = vbuf(slot);
        #pragma unroll
        for (int r = 0; r < 4; r++) {
            int i = tid + r*256;
            int row = i >> 3, c8 = (i & 7) * 8;
            cp16(smem_u32(kb) + SW128((uint32_t)(row*128 + c8*2)),
                 Kp + (size_t)(kt*128 + row)*HD + c8);
        }
        #pragma unroll
        for (int r = 0; r < 4; r++) {
            int i = tid + r*256;
            int d = i >> 4, t16 = (i & 15) * 8;
            int sub = t16 >> 6, tloc = t16 & 63;
            cp16(smem_u32(vb) + (uint32_t)(sub*8192) + SW128((uint32_t)(d*128 + tloc*2)),
                 Vp + (size_t)d*SEQ + kt*128 + t16);
        }
    };

    load_kv(0, 0); CP_COMMIT();
    load_kv(1, 1); CP_COMMIT();

    // ---- Q tile 256x64 -> smem slot2 -> register a-frags ----
    #pragma unroll
    for (int r = 0; r < 8; r++) {
        int i = tid + r*256;
        int row = i >> 3, c8 = (i & 7) * 8;
        *(uint4*)(sQ + SW128((uint32_t)(row*128 + c8*2))) = *(const uint4*)(Qp + row*HD + c8);
    }
    __syncthreads();
    uint32_t qa[2][4][4];
    {
        const uint32_t qb = smem_u32(sQ);
        #pragma unroll
        for (int a = 0; a < 2; a++) {
            int row = wid*32 + a*16 + (lane & 7) + ((lane >> 3) & 1) * 8;
            #pragma unroll
            for (int kk = 0; kk < 4; kk++) {
                uint32_t col = (uint32_t)(kk*32 + ((lane >> 4) ? 16 : 0));
                ldsm_x4(qa[a][kk], qb + SW128((uint32_t)row*128 + col));
            }
        }
    }

    float oc[2][8][4] = {};
    float lsacc[2][4] = {};
    const uint32_t ones_frag[2] = { 0x3C003C00u, 0x3C003C00u };  // fp16 1.0 x4
    const uint32_t colb = (uint32_t)((lane & 8) ? 16 : 0);
    const uint32_t rwb  = (uint32_t)(((lane & 16) ? 8 : 0) + (lane & 7));

    for (int kt = 0; kt < NKT2; kt++) {
        CP_WAIT(0);
        __syncthreads();
        if (kt + 2 < NKT2) { load_kv((kt+2)%3, kt+2); CP_COMMIT(); }
        else if (kt == NKT2 - 1) {
            // prefetch Wp slice [64 n][64 k] into slot0 (free after the kt-1 step)
            char* sW = kbuf(0);
            #pragma unroll
            for (int r = 0; r < 2; r++) {
                int i = tid + r*256;
                int row = i >> 3, c8 = (i & 7) * 8;
                cp16(smem_u32(sW) + SW128((uint32_t)(row*128 + c8*2)),
                     g_WpT + (size_t)row*WRD + hh*64 + c8);
            }
            CP_COMMIT();
        }

        const uint32_t kb_ = smem_u32(kbuf(kt%3));
        const uint32_t vb_ = smem_u32(vbuf(kt%3));

        uint32_t scf[2][16][2];
        #pragma unroll
        for (int a = 0; a < 2; a++)
            #pragma unroll
            for (int j = 0; j < 16; j++) { scf[a][j][0] = 0u; scf[a][j][1] = 0u; }
        #pragma unroll
        for (int kk = 0; kk < 4; kk++) {
            uint32_t cc = (uint32_t)(kk*32) + colb;
            #pragma unroll
            for (int j2 = 0; j2 < 8; j2++) {
                uint32_t bfr[4];
                ldsm_x4(bfr, kb_ + SW128((uint32_t)(j2*16 + rwb)*128 + cc));
                #pragma unroll
                for (int a = 0; a < 2; a++) {
                    mma16816_f16(scf[a][2*j2],   qa[a][kk], bfr);
                    mma16816_f16(scf[a][2*j2+1], qa[a][kk], bfr + 2);
                }
            }
        }

        // ---- exp one group ahead of PV ----
        uint32_t paC[2][4], paN[2][4];
        #pragma unroll
        for (int a = 0; a < 2; a++) {
            __half2 e0 = h2exp2(*(__half2*)&scf[a][0][0]);
            __half2 e1 = h2exp2(*(__half2*)&scf[a][0][1]);
            __half2 e2 = h2exp2(*(__half2*)&scf[a][1][0]);
            __half2 e3 = h2exp2(*(__half2*)&scf[a][1][1]);
            paC[a][0] = *(uint32_t*)&e0; paC[a][1] = *(uint32_t*)&e1;
            paC[a][2] = *(uint32_t*)&e2; paC[a][3] = *(uint32_t*)&e3;
        }
        #pragma unroll
        for (int tt = 0; tt < 8; tt++) {
            if (tt < 7) {
                #pragma unroll
                for (int a = 0; a < 2; a++) {
                    __half2 e0 = h2exp2(*(__half2*)&scf[a][2*tt+2][0]);
                    __half2 e1 = h2exp2(*(__half2*)&scf[a][2*tt+2][1]);
                    __half2 e2 = h2exp2(*(__half2*)&scf[a][2*tt+3][0]);
                    __half2 e3 = h2exp2(*(__half2*)&scf[a][2*tt+3][1]);
                    paN[a][0] = *(uint32_t*)&e0; paN[a][1] = *(uint32_t*)&e1;
                    paN[a][2] = *(uint32_t*)&e2; paN[a][3] = *(uint32_t*)&e3;
                }
            }
            uint32_t vblk = vb_ + (uint32_t)((tt >> 2)*8192);
            uint32_t cc = (uint32_t)((tt & 3)*32) + colb;
            #pragma unroll
            for (int jv = 0; jv < 4; jv++) {
                uint32_t bfr[4];
                ldsm_x4(bfr, vblk + SW128((uint32_t)(jv*16 + rwb)*128 + cc));
                #pragma unroll
                for (int a = 0; a < 2; a++) {
                    mma16816(oc[a][2*jv],   paC[a], bfr);
                    mma16816(oc[a][2*jv+1], paC[a], bfr + 2);
                }
            }
            #pragma unroll
            for (int a = 0; a < 2; a++) {
                mma16816(lsacc[a], paC[a], ones_frag);
                paC[a][0] = paN[a][0]; paC[a][1] = paN[a][1];
                paC[a][2] = paN[a][2]; paC[a][3] = paN[a][3];
            }
        }
    }

    // ---- fused output projection: out += (O/lsum) @ WpT[., hh*64 : hh*64+64] ----
    CP_WAIT(0);
    __syncthreads();
    {
        const uint32_t wb_ = smem_u32(kbuf(0));
        float outacc[2][8][4] = {};
        #pragma unroll
        for (int a = 0; a < 2; a++) {
            float inv0 = 1.0f / lsacc[a][0], inv1 = 1.0f / lsacc[a][2];
            #pragma unroll
            for (int kk = 0; kk < 4; kk++) {
                uint32_t oa[4];
                __half2 h0 = __floats2half2_rn(oc[a][2*kk][0]*inv0,   oc[a][2*kk][1]*inv0);
                __half2 h1 = __floats2half2_rn(oc[a][2*kk][2]*inv1,   oc[a][2*kk][3]*inv1);
                __half2 h2_ = __floats2half2_rn(oc[a][2*kk+1][0]*inv0, oc[a][2*kk+1][1]*inv0);
                __half2 h3 = __floats2half2_rn(oc[a][2*kk+1][2]*inv1, oc[a][2*kk+1][3]*inv1);
                oa[0] = *(uint32_t*)&h0;
                oa[1] = *(uint32_t*)&h1;
                oa[2] = *(uint32_t*)&h2_;
                oa[3] = *(uint32_t*)&h3;
                uint32_t cc = (uint32_t)(kk*32) + colb;
                #pragma unroll
                for (int j2 = 0; j2 < 4; j2++) {
                    uint32_t bfr[4];
                    ldsm_x4(bfr, wb_ + SW128((uint32_t)(j2*16 + rwb)*128 + cc));
                    mma16816(outacc[a][2*j2],   oa, bfr);
                    mma16816(outacc[a][2*j2+1], oa, bfr + 2);
                }
            }
        }

        int c0 = (lane & 3) * 2;
        #pragma unroll
        for (int a = 0; a < 2; a++) {
            int r = wid*32 + a*16 + (lane >> 2);
            float* O0 = out + ((size_t)(b*SEQ) + q0 + r    )*HD;
            float* O1 = out + ((size_t)(b*SEQ) + q0 + r + 8)*HD;
            #pragma unroll
            for (int j = 0; j < 8; j++) {
                int n = j*8 + c0;
                atomicAdd(O0 + n,     outacc[a][j][0]);
                atomicAdd(O0 + n + 1, outacc[a][j][1]);
                atomicAdd(O1 + n,     outacc[a][j][2]);
                atomicAdd(O1 + n + 1, outacc[a][j][3]);
            }
        }
    }
}

// ---------------- launch ----------------
extern "C" void kernel_launch(void* const* d_in, const int* in_sizes, int n_in,
                              void* d_out, int out_size)
{
    const float* x  = (const float*)d_in[0];
    const float* Wq = (const float*)d_in[1];
    const float* bq = (const float*)d_in[2];
    const float* Wk = (const float*)d_in[3];
    const float* bk = (const float*)d_in[4];
    const float* Wv = (const float*)d_in[5];
    const float* bv = (const float*)d_in[6];
    const float* Wp = (const float*)d_in[7];
    const float* bp = (const float*)d_in[8];
    float* out = (float*)d_out;

    prep2_kernel<<<1024 + 352 + 1 + 512, 256>>>(x, Wk, bk, Wv, bv, Wq, bq, Wp, bp, out);

    qkv_mma_kernel<<<dim3(MTOT/128, NQKV/64), 128>>>();

    const int attn_smem = 3 * 32768;   // 96KB dynamic ring
    cudaFuncSetAttribute(attn_mma_kernel, cudaFuncAttributeMaxDynamicSharedMemorySize, attn_smem);
    attn_mma_kernel<<<dim3(SEQ/256, NH, BATCH), 256, attn_smem>>>(out);
}